// round 10
// baseline (speedup 1.0000x reference)
#include <cuda_runtime.h>
#include <cuda_fp16.h>
#include <cstdint>

// ---------------------------------------------------------------------------
// RGCNEncoder via mma.sync fp16 tensor cores (m16n8k16, fp32 accumulate),
// ldmatrix fragment loads, BK=64 K-chunks, 4-stage cp.async pipeline,
// single __syncthreads per chunk. CTA tile 256x128, 8 warps x (64x64).
// B=128, R=6, N=256, D_IN=2048, D_H=512
//
//   x0 = relu(attn @ W_embed + b_embed)
//   layer l: Z[b,r] = x[b] @ W_rel_l[r] (r<6), Z6[b] = x[b] @ W_loop_l
//            out[b] = relu(sum_{r<6} E[b,r] @ Z[b,r] + Z6[b] + bias)
//
// Operands K-contiguous fp16. Z[b][r][d][j] for r<6 (agg's B layout);
// self-loop slice Z6 stored [n][d] (expand swaps operands for r==6).
// ---------------------------------------------------------------------------

static __device__ __half g_attnH[32768u * 2048u];
static __device__ __half g_EH[128u * 6u * 256u * 256u];
static __device__ __half g_WembT[512u * 2048u];           // [h][din]
static __device__ __half g_WT[2][7u * 512u * 512u];       // [r][dout][din]
static __device__ __half g_X0[32768u * 512u];
static __device__ __half g_X1[32768u * 512u];
static __device__ __half g_Z[128u * 7u * 512u * 256u];    // slot6 = [n][d]

#define BK 64
#define RSTR 72   // BK + 8 pad (halves): 144B row stride, conflict-free ldmatrix

static constexpr uint32_t A_BYTES = 256u * RSTR * 2;       // 36864
static constexpr uint32_t B_BYTES = 128u * RSTR * 2;       // 18432
static constexpr uint32_t STAGE_BYTES = A_BYTES + B_BYTES; // 55296
static constexpr int SMEM_BYTES = 4 * STAGE_BYTES;         // 221184

// ---- low-level helpers -----------------------------------------------------

__device__ __forceinline__ uint32_t smem_u32(const void* p) {
    uint32_t a;
    asm("{ .reg .u64 t; cvta.to.shared.u64 t, %1; cvt.u32.u64 %0, t; }"
        : "=r"(a) : "l"(p));
    return a;
}
__device__ __forceinline__ void cp_async16(uint32_t dst, const void* src) {
    asm volatile("cp.async.cg.shared.global [%0], [%1], 16;" ::"r"(dst), "l"(src));
}
__device__ __forceinline__ void cp_commit() {
    asm volatile("cp.async.commit_group;" ::: "memory");
}
template <int N>
__device__ __forceinline__ void cp_wait() {
    asm volatile("cp.async.wait_group %0;" ::"n"(N) : "memory");
}
__device__ __forceinline__ uint32_t h2u(__half2 h) {
    return *reinterpret_cast<uint32_t*>(&h);
}
__device__ __forceinline__ void ldm_x4(uint32_t& r0, uint32_t& r1, uint32_t& r2,
                                       uint32_t& r3, uint32_t addr) {
    asm volatile("ldmatrix.sync.aligned.m8n8.x4.shared.b16 {%0,%1,%2,%3}, [%4];"
                 : "=r"(r0), "=r"(r1), "=r"(r2), "=r"(r3) : "r"(addr));
}
__device__ __forceinline__ void mma16(float* c, const uint32_t* a, const uint32_t* b) {
    asm volatile(
        "mma.sync.aligned.m16n8k16.row.col.f32.f16.f16.f32 "
        "{%0,%1,%2,%3}, {%4,%5,%6,%7}, {%8,%9}, {%0,%1,%2,%3};"
        : "+f"(c[0]), "+f"(c[1]), "+f"(c[2]), "+f"(c[3])
        : "r"(a[0]), "r"(a[1]), "r"(a[2]), "r"(a[3]), "r"(b[0]), "r"(b[1]));
}

// ROWS x 64-half tile (128B/row) -> padded smem, 256 threads
template <int ROWS>
__device__ __forceinline__ void ld_tile(uint32_t dst, const __half* __restrict__ src,
                                        int ldk, int tid) {
#pragma unroll
    for (int i = 0; i < ROWS * 8 / 256; i++) {
        int idx = tid + i * 256;
        int row = idx >> 3, seg = idx & 7;
        cp_async16(dst + (uint32_t)(row * (RSTR * 2) + seg * 16),
                   src + (size_t)row * ldk + seg * 8);
    }
}

// ---- shared mainloop -------------------------------------------------------
// 4-stage ring, single barrier per chunk. Load target (c+3)%4 == (c-1)%4 was
// consumed at iter c-1; the barrier at iter c proves all warps left it.

template <class F>
__device__ __forceinline__ void gemm_main(const F& f, int nc, char* smraw,
                                          float acc[4][8][4]) {
    const int tid = threadIdx.x;
    const uint32_t sbase = smem_u32(smraw);
    const int lane = tid & 31, wid = tid >> 5;
    const int wm = (wid >> 1) * 64, wn = (wid & 1) * 64;

    const int l7 = lane & 7, lb3 = (lane >> 3) & 1, lb4 = lane >> 4;
    const uint32_t aOff = (uint32_t)((wm + l7 + lb3 * 8) * RSTR + lb4 * 8) * 2;
    const uint32_t bOff = A_BYTES +
        (uint32_t)((wn + l7 + lb4 * 8) * RSTR + lb3 * 8) * 2;

    // prologue: stages 0..2
#pragma unroll
    for (int p = 0; p < 3; p++) {
        if (p < nc) {
            ld_tile<256>(sbase + p * STAGE_BYTES, f.a(p), f.lda, tid);
            ld_tile<128>(sbase + p * STAGE_BYTES + A_BYTES, f.b(p), f.ldb, tid);
        }
        cp_commit();
    }

    int stage = 0, nxt = 3;
    for (int c = 0; c < nc; c++) {
        if (c <= nc - 3) cp_wait<2>();
        else if (c == nc - 2) cp_wait<1>();
        else cp_wait<0>();
        __syncthreads();
        if (c + 3 < nc) {
            ld_tile<256>(sbase + nxt * STAGE_BYTES, f.a(c + 3), f.lda, tid);
            ld_tile<128>(sbase + nxt * STAGE_BYTES + A_BYTES, f.b(c + 3), f.ldb, tid);
            cp_commit();
        }
        const uint32_t abase = sbase + stage * STAGE_BYTES + aOff;
        const uint32_t bbase = sbase + stage * STAGE_BYTES + bOff;
#pragma unroll
        for (int kk = 0; kk < BK; kk += 16) {
            uint32_t a[4][4], b[8][2];
#pragma unroll
            for (int mt = 0; mt < 4; mt++)
                ldm_x4(a[mt][0], a[mt][1], a[mt][2], a[mt][3],
                       abase + (uint32_t)(mt * 16 * RSTR + kk) * 2);
#pragma unroll
            for (int p = 0; p < 4; p++)
                ldm_x4(b[2 * p][0], b[2 * p][1], b[2 * p + 1][0], b[2 * p + 1][1],
                       bbase + (uint32_t)(p * 16 * RSTR + kk) * 2);
#pragma unroll
            for (int mt = 0; mt < 4; mt++)
#pragma unroll
                for (int nt = 0; nt < 8; nt++) mma16(acc[mt][nt], a[mt], b[nt]);
        }
        stage = (stage + 1) & 3;
        nxt = (nxt + 1) & 3;
    }
}

__device__ __forceinline__ void zero_acc(float acc[4][8][4]) {
#pragma unroll
    for (int i = 0; i < 4; i++)
#pragma unroll
        for (int j = 0; j < 8; j++)
#pragma unroll
            for (int k = 0; k < 4; k++) acc[i][j][k] = 0.f;
}

// ---- address functors ------------------------------------------------------

struct LinAddr {
    const __half *A, *B;
    int lda, ldb;
    __device__ const __half* a(int c) const { return A + c * BK; }
    __device__ const __half* b(int c) const { return B + c * BK; }
};
struct AggAddr {
    const __half *Eb, *Zb;
    int lda, ldb;
    __device__ const __half* a(int c) const {
        return Eb + (size_t)(c >> 2) * 65536u + (c & 3) * BK;
    }
    __device__ const __half* b(int c) const {
        return Zb + (size_t)(c >> 2) * 131072u + (c & 3) * BK;
    }
};

// ---- kernels ---------------------------------------------------------------

// embed: X0[node][h] = relu(attnH @ WembT^T + bias), fp16 out
// grid (4, 128): bx = 128-col tile, by = 256-row tile
__global__ void __launch_bounds__(256, 1) k_embed(const __half* __restrict__ attn,
                                                  const __half* __restrict__ WT,
                                                  const float* __restrict__ bias,
                                                  __half* __restrict__ out) {
    extern __shared__ char smraw[];
    const int bx = blockIdx.x, by = blockIdx.y;
    float acc[4][8][4];
    zero_acc(acc);

    LinAddr f{attn + (size_t)by * 256 * 2048, WT + (size_t)bx * 128 * 2048,
              2048, 2048};
    gemm_main(f, 32, smraw, acc);

    const int tid = threadIdx.x, lane = tid & 31, wid = tid >> 5;
    const int gid = lane >> 2, tig = lane & 3;
    const int wm = (wid >> 1) * 64, wn = (wid & 1) * 64;
#pragma unroll
    for (int mt = 0; mt < 4; mt++) {
        int row = by * 256 + wm + mt * 16 + gid;
#pragma unroll
        for (int nt = 0; nt < 8; nt++) {
            int col = bx * 128 + wn + nt * 8 + 2 * tig;
            float b0 = bias[col], b1 = bias[col + 1];
            __half2 h0 = __floats2half2_rn(fmaxf(acc[mt][nt][0] + b0, 0.f),
                                           fmaxf(acc[mt][nt][1] + b1, 0.f));
            __half2 h1 = __floats2half2_rn(fmaxf(acc[mt][nt][2] + b0, 0.f),
                                           fmaxf(acc[mt][nt][3] + b1, 0.f));
            *(uint32_t*)&out[(size_t)row * 512 + col] = h2u(h0);
            *(uint32_t*)&out[(size_t)(row + 8) * 512 + col] = h2u(h1);
        }
    }
}

// expand: grid (16, 256)
//   bx<12 : r = bx>>1, d0 = (bx&1)*256; M=d (256 rows of WT[r]), N=node
//           (128 at by*128)  -> Z[b][r][d][j]
//   bx>=12: r==6, d0 = (bx-12)*128; M=node (256 at by*256, by<128), N=d (128)
//           -> Z6[b][n][d]
__global__ void __launch_bounds__(256, 1) k_expand(const __half* __restrict__ X,
                                                   const __half* __restrict__ WT,
                                                   __half* __restrict__ Z) {
    extern __shared__ char smraw[];
    const int bx = blockIdx.x, by = blockIdx.y;
    const bool loop_rel = (bx >= 12);
    if (loop_rel && by >= 128) return;
    const int r = loop_rel ? 6 : (bx >> 1);
    const int d0 = loop_rel ? (bx - 12) * 128 : (bx & 1) * 256;

    float acc[4][8][4];
    zero_acc(acc);

    const __half* Wp = WT + (size_t)r * 262144u + (size_t)d0 * 512;
    LinAddr f = loop_rel
        ? LinAddr{X + (size_t)by * 256 * 512, Wp, 512, 512}
        : LinAddr{Wp, X + (size_t)by * 128 * 512, 512, 512};
    gemm_main(f, 8, smraw, acc);

    const int tid = threadIdx.x, lane = tid & 31, wid = tid >> 5;
    const int gid = lane >> 2, tig = lane & 3;
    const int wm = (wid >> 1) * 64, wn = (wid & 1) * 64;
    if (!loop_rel) {
#pragma unroll
        for (int mt = 0; mt < 4; mt++) {
            int d = d0 + wm + mt * 16 + gid;
#pragma unroll
            for (int nt = 0; nt < 8; nt++) {
                int m = by * 128 + wn + nt * 8 + 2 * tig;   // global node
                int b = m >> 8, j = m & 255;
                size_t zb = ((size_t)b * 7 + r) * 512u;
                __half2 h0 = __floats2half2_rn(acc[mt][nt][0], acc[mt][nt][1]);
                __half2 h1 = __floats2half2_rn(acc[mt][nt][2], acc[mt][nt][3]);
                *(uint32_t*)&Z[(zb + d) * 256u + j] = h2u(h0);
                *(uint32_t*)&Z[(zb + d + 8) * 256u + j] = h2u(h1);
            }
        }
    } else {
#pragma unroll
        for (int mt = 0; mt < 4; mt++) {
            int m = by * 256 + wm + mt * 16 + gid;          // global node
            int b = m >> 8, n = m & 255;
            size_t z6 = ((size_t)b * 7 + 6) * 131072u;
#pragma unroll
            for (int nt = 0; nt < 8; nt++) {
                int d = d0 + wn + nt * 8 + 2 * tig;
                __half2 h0 = __floats2half2_rn(acc[mt][nt][0], acc[mt][nt][1]);
                __half2 h1 = __floats2half2_rn(acc[mt][nt][2], acc[mt][nt][3]);
                *(uint32_t*)&Z[z6 + (size_t)n * 512 + d] = h2u(h0);
                *(uint32_t*)&Z[z6 + (size_t)(n + 8) * 512 + d] = h2u(h1);
            }
        }
    }
}

// agg: grid (4, 1, 128). One 256-row M tile per batch.
// out[b,i,d] = relu(sum_{r<6,j} EH[b,r,i,j]*Z[b,r,d,j] + Z6[b,i,d] + bias[d])
template <bool HALF_OUT>
__global__ void __launch_bounds__(256, 1) k_agg(const __half* __restrict__ EH,
                                                const __half* __restrict__ Z,
                                                const float* __restrict__ bias,
                                                void* __restrict__ outv) {
    extern __shared__ char smraw[];
    const int bx = blockIdx.x, b = blockIdx.z;
    float acc[4][8][4];
    zero_acc(acc);

    AggAddr f{EH + (size_t)b * 393216u,
              Z + (size_t)b * 917504u + (size_t)(bx * 128) * 256u, 256, 256};
    gemm_main(f, 24, smraw, acc);

    const __half* Z6 = Z + (size_t)b * 917504u + 6u * 131072u;   // [n][d]
    const int tid = threadIdx.x, lane = tid & 31, wid = tid >> 5;
    const int gid = lane >> 2, tig = lane & 3;
    const int wm = (wid >> 1) * 64, wn = (wid & 1) * 64;
#pragma unroll
    for (int mt = 0; mt < 4; mt++) {
        int i = wm + mt * 16 + gid;
#pragma unroll
        for (int nt = 0; nt < 8; nt++) {
            int d = bx * 128 + wn + nt * 8 + 2 * tig;
            float b0 = bias[d], b1 = bias[d + 1];
            __half2 s0 = *(const __half2*)&Z6[(size_t)i * 512 + d];
            __half2 s1 = *(const __half2*)&Z6[(size_t)(i + 8) * 512 + d];
            float2 f0 = __half22float2(s0), f1 = __half22float2(s1);
            float r0 = fmaxf(acc[mt][nt][0] + f0.x + b0, 0.f);
            float r1 = fmaxf(acc[mt][nt][1] + f0.y + b1, 0.f);
            float r2 = fmaxf(acc[mt][nt][2] + f1.x + b0, 0.f);
            float r3 = fmaxf(acc[mt][nt][3] + f1.y + b1, 0.f);
            size_t o0 = ((size_t)b * 256 + i) * 512 + d;
            size_t o1 = ((size_t)b * 256 + i + 8) * 512 + d;
            if (HALF_OUT) {
                __half* out = (__half*)outv;
                *(uint32_t*)&out[o0] = h2u(__floats2half2_rn(r0, r1));
                *(uint32_t*)&out[o1] = h2u(__floats2half2_rn(r2, r3));
            } else {
                float* out = (float*)outv;
                *(float2*)&out[o0] = make_float2(r0, r1);
                *(float2*)&out[o1] = make_float2(r2, r3);
            }
        }
    }
}

// ---- conversion / transpose pre-kernels ------------------------------------

__global__ void k_cvt8(const float* __restrict__ src, __half* __restrict__ dst,
                       int n8) {
    int i = blockIdx.x * blockDim.x + threadIdx.x;
    if (i < n8) {
        const float4* s4 = (const float4*)src;
        float4 v0 = s4[2 * i], v1 = s4[2 * i + 1];
        uint4 o;
        o.x = h2u(__floats2half2_rn(v0.x, v0.y));
        o.y = h2u(__floats2half2_rn(v0.z, v0.w));
        o.z = h2u(__floats2half2_rn(v1.x, v1.y));
        o.w = h2u(__floats2half2_rn(v1.z, v1.w));
        ((uint4*)dst)[i] = o;
    }
}

// E fp32 [b][6][i][j] -> fp16 [b][6][i][j]
__global__ void k_cvtE(const float* __restrict__ E, __half* __restrict__ EH) {
    size_t i = (size_t)blockIdx.x * blockDim.x + threadIdx.x;  // float4 index
    const float4* s4 = (const float4*)E;
    float4 v = s4[i];
    uint2 o;
    o.x = h2u(__floats2half2_rn(v.x, v.y));
    o.y = h2u(__floats2half2_rn(v.z, v.w));
    ((uint2*)EH)[i] = o;
}

// batched transpose+convert of ALL weights in one launch.
__global__ void k_tcvt_all(const float* __restrict__ Wemb,
                           const float* __restrict__ Wr0,
                           const float* __restrict__ Wl0,
                           const float* __restrict__ Wr1,
                           const float* __restrict__ Wl1,
                           __half* __restrict__ WembT,
                           __half* __restrict__ WT) {
    __shared__ float t[32][33];
    int bid = blockIdx.x;
    const float* src;
    __half* dst;
    int R, C, tx, ty;
    if (bid < 1024) {
        src = Wemb; dst = WembT; R = 2048; C = 512;
        tx = bid & 15; ty = bid >> 4;
    } else {
        int idx = bid - 1024;
        int m = idx >> 8, tile = idx & 255;
        int layer = m / 7, r = m % 7;
        src = (r < 6) ? (layer ? Wr1 : Wr0) + (size_t)r * 262144u
                      : (layer ? Wl1 : Wl0);
        dst = WT + (size_t)m * 262144u;
        R = 512; C = 512;
        tx = tile & 15; ty = tile >> 4;
    }
    int bx = tx * 32, by = ty * 32;
    int x = threadIdx.x, y = threadIdx.y;
#pragma unroll
    for (int j = 0; j < 32; j += 8)
        t[y + j][x] = src[(size_t)(by + y + j) * C + bx + x];
    __syncthreads();
#pragma unroll
    for (int j = 0; j < 32; j += 8)
        dst[(size_t)(bx + y + j) * R + by + x] = __float2half_rn(t[x][y + j]);
}

// ---------------------------------------------------------------------------

extern "C" void kernel_launch(void* const* d_in, const int* in_sizes, int n_in,
                              void* d_out, int out_size) {
    const float* attn = (const float*)d_in[0];
    const float* E    = (const float*)d_in[1];
    const float* Wemb = (const float*)d_in[2];
    const float* bemb = (const float*)d_in[3];
    const float* Wr0  = (const float*)d_in[4];
    const float* Wl0  = (const float*)d_in[5];
    const float* b0   = (const float*)d_in[6];
    const float* Wr1  = (const float*)d_in[7];
    const float* Wl1  = (const float*)d_in[8];
    const float* b1   = (const float*)d_in[9];
    float* out = (float*)d_out;

    __half *attnH, *EH, *WembT, *WT, *X0, *X1, *Z;
    cudaGetSymbolAddress((void**)&attnH, g_attnH);
    cudaGetSymbolAddress((void**)&EH, g_EH);
    cudaGetSymbolAddress((void**)&WembT, g_WembT);
    cudaGetSymbolAddress((void**)&WT, g_WT);
    cudaGetSymbolAddress((void**)&X0, g_X0);
    cudaGetSymbolAddress((void**)&X1, g_X1);
    cudaGetSymbolAddress((void**)&Z, g_Z);
    __half* WT0 = WT;
    __half* WT1 = WT + 7u * 262144u;

    cudaFuncSetAttribute(k_embed, cudaFuncAttributeMaxDynamicSharedMemorySize, SMEM_BYTES);
    cudaFuncSetAttribute(k_expand, cudaFuncAttributeMaxDynamicSharedMemorySize, SMEM_BYTES);
    cudaFuncSetAttribute(k_agg<true>, cudaFuncAttributeMaxDynamicSharedMemorySize, SMEM_BYTES);
    cudaFuncSetAttribute(k_agg<false>, cudaFuncAttributeMaxDynamicSharedMemorySize, SMEM_BYTES);

    k_tcvt_all<<<1024 + 14 * 256, dim3(32, 8)>>>(Wemb, Wr0, Wl0, Wr1, Wl1,
                                                 WembT, WT);
    k_cvt8<<<32768, 256>>>(attn, attnH, 32768 * 2048 / 8);
    k_cvtE<<<128u * 6u * 256u * 256u / 4u / 256u, 256>>>(E, EH);

    k_embed<<<dim3(4, 128), 256, SMEM_BYTES>>>(attnH, WembT, bemb, X0);

    k_expand<<<dim3(16, 256), 256, SMEM_BYTES>>>(X0, WT0, Z);
    k_agg<true><<<dim3(4, 1, 128), 256, SMEM_BYTES>>>(EH, Z, b0, X1);

    k_expand<<<dim3(16, 256), 256, SMEM_BYTES>>>(X1, WT1, Z);
    k_agg<false><<<dim3(4, 1, 128), 256, SMEM_BYTES>>>(EH, Z, b1, out);
}

// round 11
// speedup vs baseline: 1.1348x; 1.1348x over previous
#include <cuda_runtime.h>
#include <cuda_fp16.h>
#include <cstdint>

// ---------------------------------------------------------------------------
// RGCNEncoder via mma.sync fp16 tensor cores (m16n8k16, fp32 accumulate),
// ldmatrix fragment loads, BK=64 K-chunks, 3-stage cp.async pipeline,
// single __syncthreads per chunk. CTA tile 128x128, 8 warps x (64x32),
// __launch_bounds__(256,2) -> 2 CTAs/SM -> 4 warps/SMSP.
// B=128, R=6, N=256, D_IN=2048, D_H=512
//
//   x0 = relu(attn @ W_embed + b_embed)
//   layer l: Z[b,r] = x[b] @ W_rel_l[r] (r<6), Z6[b] = x[b] @ W_loop_l
//            out[b] = relu(sum_{r<6} E[b,r] @ Z[b,r] + Z6[b] + bias)
//
// Operands K-contiguous fp16. Z[b][r][d][j] for r<6 (agg's B layout);
// self-loop slice Z6 stored [n][d] (expand swaps operands for r==6).
// ---------------------------------------------------------------------------

static __device__ __half g_attnH[32768u * 2048u];
static __device__ __half g_EH[128u * 6u * 256u * 256u];
static __device__ __half g_WembT[512u * 2048u];           // [h][din]
static __device__ __half g_WT[2][7u * 512u * 512u];       // [r][dout][din]
static __device__ __half g_X0[32768u * 512u];
static __device__ __half g_X1[32768u * 512u];
static __device__ __half g_Z[128u * 7u * 512u * 256u];    // slot6 = [n][d]

#define BK 64
#define RSTR 72   // BK + 8 pad (halves): 144B row stride, conflict-free ldmatrix

static constexpr uint32_t AS_BYTES = 128u * RSTR * 2;      // 18432 per operand
static constexpr uint32_t STAGE_BYTES = 2 * AS_BYTES;      // 36864
static constexpr int SMEM_BYTES = 3 * STAGE_BYTES;         // 110592 (x2 CTA = 221K)

// ---- low-level helpers -----------------------------------------------------

__device__ __forceinline__ uint32_t smem_u32(const void* p) {
    uint32_t a;
    asm("{ .reg .u64 t; cvta.to.shared.u64 t, %1; cvt.u32.u64 %0, t; }"
        : "=r"(a) : "l"(p));
    return a;
}
__device__ __forceinline__ void cp_async16(uint32_t dst, const void* src) {
    asm volatile("cp.async.cg.shared.global [%0], [%1], 16;" ::"r"(dst), "l"(src));
}
__device__ __forceinline__ void cp_commit() {
    asm volatile("cp.async.commit_group;" ::: "memory");
}
template <int N>
__device__ __forceinline__ void cp_wait() {
    asm volatile("cp.async.wait_group %0;" ::"n"(N) : "memory");
}
__device__ __forceinline__ uint32_t h2u(__half2 h) {
    return *reinterpret_cast<uint32_t*>(&h);
}
__device__ __forceinline__ void ldm_x4(uint32_t& r0, uint32_t& r1, uint32_t& r2,
                                       uint32_t& r3, uint32_t addr) {
    asm volatile("ldmatrix.sync.aligned.m8n8.x4.shared.b16 {%0,%1,%2,%3}, [%4];"
                 : "=r"(r0), "=r"(r1), "=r"(r2), "=r"(r3) : "r"(addr));
}
__device__ __forceinline__ void mma16(float* c, const uint32_t* a, const uint32_t* b) {
    asm volatile(
        "mma.sync.aligned.m16n8k16.row.col.f32.f16.f16.f32 "
        "{%0,%1,%2,%3}, {%4,%5,%6,%7}, {%8,%9}, {%0,%1,%2,%3};"
        : "+f"(c[0]), "+f"(c[1]), "+f"(c[2]), "+f"(c[3])
        : "r"(a[0]), "r"(a[1]), "r"(a[2]), "r"(a[3]), "r"(b[0]), "r"(b[1]));
}

// 128 rows x 64 halves (128B/row) tile -> padded smem, 256 threads
__device__ __forceinline__ void ld_tile(uint32_t dst, const __half* __restrict__ src,
                                        int ldk, int tid) {
#pragma unroll
    for (int i = 0; i < 4; i++) {
        int idx = tid + i * 256;
        int row = idx >> 3, seg = idx & 7;
        cp_async16(dst + (uint32_t)(row * (RSTR * 2) + seg * 16),
                   src + (size_t)row * ldk + seg * 8);
    }
}

// ---- shared mainloop -------------------------------------------------------
// 8 warps, each a 64x32 warp tile (wm=(wid>>2)*64, wn=(wid&3)*32).
// Per k16 step: 4 A-ldmatrix.x4 + 2 B-ldmatrix.x4 feed 16 MMAs.
// 3-stage ring, single barrier per chunk.

template <class F>
__device__ __forceinline__ void gemm_main(const F& f, int nc, char* smraw,
                                          float acc[4][4][4]) {
    const int tid = threadIdx.x;
    const uint32_t sbase = smem_u32(smraw);
    const int lane = tid & 31, wid = tid >> 5;
    const int wm = (wid >> 2) * 64, wn = (wid & 3) * 32;

    const int l7 = lane & 7, lb3 = (lane >> 3) & 1, lb4 = lane >> 4;
    const uint32_t aOff = (uint32_t)((wm + l7 + lb3 * 8) * RSTR + lb4 * 8) * 2;
    const uint32_t bOff = AS_BYTES +
        (uint32_t)((wn + l7 + lb4 * 8) * RSTR + lb3 * 8) * 2;

    // prologue: stages 0, 1
#pragma unroll
    for (int p = 0; p < 2; p++) {
        if (p < nc) {
            ld_tile(sbase + p * STAGE_BYTES, f.a(p), f.lda, tid);
            ld_tile(sbase + p * STAGE_BYTES + AS_BYTES, f.b(p), f.ldb, tid);
        }
        cp_commit();
    }

    int stage = 0, nxt = 2;
    for (int c = 0; c < nc; c++) {
        if (c + 1 < nc) cp_wait<1>(); else cp_wait<0>();
        __syncthreads();
        if (c + 2 < nc) {
            ld_tile(sbase + nxt * STAGE_BYTES, f.a(c + 2), f.lda, tid);
            ld_tile(sbase + nxt * STAGE_BYTES + AS_BYTES, f.b(c + 2), f.ldb, tid);
            cp_commit();
        }
        const uint32_t abase = sbase + stage * STAGE_BYTES + aOff;
        const uint32_t bbase = sbase + stage * STAGE_BYTES + bOff;
#pragma unroll
        for (int kk = 0; kk < BK; kk += 16) {
            uint32_t a[4][4], b[4][2];
#pragma unroll
            for (int mt = 0; mt < 4; mt++)
                ldm_x4(a[mt][0], a[mt][1], a[mt][2], a[mt][3],
                       abase + (uint32_t)(mt * 16 * RSTR + kk) * 2);
#pragma unroll
            for (int p = 0; p < 2; p++)
                ldm_x4(b[2 * p][0], b[2 * p][1], b[2 * p + 1][0], b[2 * p + 1][1],
                       bbase + (uint32_t)(p * 16 * RSTR + kk) * 2);
#pragma unroll
            for (int mt = 0; mt < 4; mt++)
#pragma unroll
                for (int nt = 0; nt < 4; nt++) mma16(acc[mt][nt], a[mt], b[nt]);
        }
        stage = (stage == 2) ? 0 : stage + 1;
        nxt = (nxt == 2) ? 0 : nxt + 1;
    }
}

__device__ __forceinline__ void zero_acc(float acc[4][4][4]) {
#pragma unroll
    for (int i = 0; i < 4; i++)
#pragma unroll
        for (int j = 0; j < 4; j++)
#pragma unroll
            for (int k = 0; k < 4; k++) acc[i][j][k] = 0.f;
}

// ---- address functors ------------------------------------------------------

struct LinAddr {
    const __half *A, *B;
    int lda, ldb;
    __device__ const __half* a(int c) const { return A + c * BK; }
    __device__ const __half* b(int c) const { return B + c * BK; }
};
struct AggAddr {
    const __half *Eb, *Zb;
    int lda, ldb;
    __device__ const __half* a(int c) const {
        return Eb + (size_t)(c >> 2) * 65536u + (c & 3) * BK;
    }
    __device__ const __half* b(int c) const {
        return Zb + (size_t)(c >> 2) * 131072u + (c & 3) * BK;
    }
};

// ---- kernels ---------------------------------------------------------------

// embed: X0[node][h] = relu(attnH @ WembT^T + bias), fp16 out. grid (4,256)
__global__ void __launch_bounds__(256, 2) k_embed(const __half* __restrict__ attn,
                                                  const __half* __restrict__ WT,
                                                  const float* __restrict__ bias,
                                                  __half* __restrict__ out) {
    extern __shared__ char smraw[];
    const int bx = blockIdx.x, by = blockIdx.y;
    float acc[4][4][4];
    zero_acc(acc);

    LinAddr f{attn + (size_t)by * 128 * 2048, WT + (size_t)bx * 128 * 2048,
              2048, 2048};
    gemm_main(f, 32, smraw, acc);

    const int tid = threadIdx.x, lane = tid & 31, wid = tid >> 5;
    const int gid = lane >> 2, tig = lane & 3;
    const int wm = (wid >> 2) * 64, wn = (wid & 3) * 32;
#pragma unroll
    for (int mt = 0; mt < 4; mt++) {
        int row = by * 128 + wm + mt * 16 + gid;
#pragma unroll
        for (int nt = 0; nt < 4; nt++) {
            int col = bx * 128 + wn + nt * 8 + 2 * tig;
            float b0 = bias[col], b1 = bias[col + 1];
            __half2 h0 = __floats2half2_rn(fmaxf(acc[mt][nt][0] + b0, 0.f),
                                           fmaxf(acc[mt][nt][1] + b1, 0.f));
            __half2 h1 = __floats2half2_rn(fmaxf(acc[mt][nt][2] + b0, 0.f),
                                           fmaxf(acc[mt][nt][3] + b1, 0.f));
            *(uint32_t*)&out[(size_t)row * 512 + col] = h2u(h0);
            *(uint32_t*)&out[(size_t)(row + 8) * 512 + col] = h2u(h1);
        }
    }
}

// expand: grid (28, 256). r = bx>>2, d0 = (bx&3)*128.
//   r<6 : Z[b][r][d][j] = (WT[r] @ X^T)[d][node]   (transposed GEMM)
//   r==6: Z6[b][n][d]   = (X @ WT6^T)[node][d]     (natural GEMM, coalesced)
__global__ void __launch_bounds__(256, 2) k_expand(const __half* __restrict__ X,
                                                   const __half* __restrict__ WT,
                                                   __half* __restrict__ Z) {
    extern __shared__ char smraw[];
    const int bx = blockIdx.x, by = blockIdx.y;
    const int r = bx >> 2, d0 = (bx & 3) * 128;
    float acc[4][4][4];
    zero_acc(acc);

    const __half* Xp = X + (size_t)by * 128 * 512;
    const __half* Wp = WT + (size_t)r * 262144u + (size_t)d0 * 512;
    const bool loop_rel = (r == 6);
    LinAddr f = loop_rel ? LinAddr{Xp, Wp, 512, 512} : LinAddr{Wp, Xp, 512, 512};
    gemm_main(f, 8, smraw, acc);

    const int tid = threadIdx.x, lane = tid & 31, wid = tid >> 5;
    const int gid = lane >> 2, tig = lane & 3;
    const int wm = (wid >> 2) * 64, wn = (wid & 3) * 32;
    if (!loop_rel) {
#pragma unroll
        for (int mt = 0; mt < 4; mt++) {
            int d = d0 + wm + mt * 16 + gid;
#pragma unroll
            for (int nt = 0; nt < 4; nt++) {
                int m = by * 128 + wn + nt * 8 + 2 * tig;   // global node
                int b = m >> 8, j = m & 255;
                size_t zb = ((size_t)b * 7 + r) * 512u;
                __half2 h0 = __floats2half2_rn(acc[mt][nt][0], acc[mt][nt][1]);
                __half2 h1 = __floats2half2_rn(acc[mt][nt][2], acc[mt][nt][3]);
                *(uint32_t*)&Z[(zb + d) * 256u + j] = h2u(h0);
                *(uint32_t*)&Z[(zb + d + 8) * 256u + j] = h2u(h1);
            }
        }
    } else {
#pragma unroll
        for (int mt = 0; mt < 4; mt++) {
            int m = by * 128 + wm + mt * 16 + gid;          // global node
            int b = m >> 8, n = m & 255;
            size_t z6 = ((size_t)b * 7 + 6) * 131072u;
#pragma unroll
            for (int nt = 0; nt < 4; nt++) {
                int d = d0 + wn + nt * 8 + 2 * tig;
                __half2 h0 = __floats2half2_rn(acc[mt][nt][0], acc[mt][nt][1]);
                __half2 h1 = __floats2half2_rn(acc[mt][nt][2], acc[mt][nt][3]);
                *(uint32_t*)&Z[z6 + (size_t)n * 512 + d] = h2u(h0);
                *(uint32_t*)&Z[z6 + (size_t)(n + 8) * 512 + d] = h2u(h1);
            }
        }
    }
}

// agg: grid (4, 2, 128).
// out[b,i,d] = relu(sum_{r<6,j} EH[b,r,i,j]*Z[b,r,d,j] + Z6[b,i,d] + bias[d])
template <bool HALF_OUT>
__global__ void __launch_bounds__(256, 2) k_agg(const __half* __restrict__ EH,
                                                const __half* __restrict__ Z,
                                                const float* __restrict__ bias,
                                                void* __restrict__ outv) {
    extern __shared__ char smraw[];
    const int bx = blockIdx.x, by = blockIdx.y, b = blockIdx.z;
    float acc[4][4][4];
    zero_acc(acc);

    AggAddr f{EH + (size_t)b * 393216u + (size_t)(by * 128) * 256u,
              Z + (size_t)b * 917504u + (size_t)(bx * 128) * 256u, 256, 256};
    gemm_main(f, 24, smraw, acc);

    const __half* Z6 = Z + (size_t)b * 917504u + 6u * 131072u;   // [n][d]
    const int tid = threadIdx.x, lane = tid & 31, wid = tid >> 5;
    const int gid = lane >> 2, tig = lane & 3;
    const int wm = (wid >> 2) * 64, wn = (wid & 3) * 32;
#pragma unroll
    for (int mt = 0; mt < 4; mt++) {
        int i = by * 128 + wm + mt * 16 + gid;
#pragma unroll
        for (int nt = 0; nt < 4; nt++) {
            int d = bx * 128 + wn + nt * 8 + 2 * tig;
            float b0 = bias[d], b1 = bias[d + 1];
            __half2 s0 = *(const __half2*)&Z6[(size_t)i * 512 + d];
            __half2 s1 = *(const __half2*)&Z6[(size_t)(i + 8) * 512 + d];
            float2 f0 = __half22float2(s0), f1 = __half22float2(s1);
            float r0 = fmaxf(acc[mt][nt][0] + f0.x + b0, 0.f);
            float r1 = fmaxf(acc[mt][nt][1] + f0.y + b1, 0.f);
            float r2 = fmaxf(acc[mt][nt][2] + f1.x + b0, 0.f);
            float r3 = fmaxf(acc[mt][nt][3] + f1.y + b1, 0.f);
            size_t o0 = ((size_t)b * 256 + i) * 512 + d;
            size_t o1 = ((size_t)b * 256 + i + 8) * 512 + d;
            if (HALF_OUT) {
                __half* out = (__half*)outv;
                *(uint32_t*)&out[o0] = h2u(__floats2half2_rn(r0, r1));
                *(uint32_t*)&out[o1] = h2u(__floats2half2_rn(r2, r3));
            } else {
                float* out = (float*)outv;
                *(float2*)&out[o0] = make_float2(r0, r1);
                *(float2*)&out[o1] = make_float2(r2, r3);
            }
        }
    }
}

// ---- conversion / transpose pre-kernels ------------------------------------

__global__ void k_cvt8(const float* __restrict__ src, __half* __restrict__ dst,
                       int n8) {
    int i = blockIdx.x * blockDim.x + threadIdx.x;
    if (i < n8) {
        const float4* s4 = (const float4*)src;
        float4 v0 = s4[2 * i], v1 = s4[2 * i + 1];
        uint4 o;
        o.x = h2u(__floats2half2_rn(v0.x, v0.y));
        o.y = h2u(__floats2half2_rn(v0.z, v0.w));
        o.z = h2u(__floats2half2_rn(v1.x, v1.y));
        o.w = h2u(__floats2half2_rn(v1.z, v1.w));
        ((uint4*)dst)[i] = o;
    }
}

// E fp32 [b][6][i][j] -> fp16 [b][6][i][j]
__global__ void k_cvtE(const float* __restrict__ E, __half* __restrict__ EH) {
    size_t i = (size_t)blockIdx.x * blockDim.x + threadIdx.x;  // float4 index
    const float4* s4 = (const float4*)E;
    float4 v = s4[i];
    uint2 o;
    o.x = h2u(__floats2half2_rn(v.x, v.y));
    o.y = h2u(__floats2half2_rn(v.z, v.w));
    ((uint2*)EH)[i] = o;
}

// batched transpose+convert of ALL weights in one launch.
__global__ void k_tcvt_all(const float* __restrict__ Wemb,
                           const float* __restrict__ Wr0,
                           const float* __restrict__ Wl0,
                           const float* __restrict__ Wr1,
                           const float* __restrict__ Wl1,
                           __half* __restrict__ WembT,
                           __half* __restrict__ WT) {
    __shared__ float t[32][33];
    int bid = blockIdx.x;
    const float* src;
    __half* dst;
    int R, C, tx, ty;
    if (bid < 1024) {
        src = Wemb; dst = WembT; R = 2048; C = 512;
        tx = bid & 15; ty = bid >> 4;
    } else {
        int idx = bid - 1024;
        int m = idx >> 8, tile = idx & 255;
        int layer = m / 7, r = m % 7;
        src = (r < 6) ? (layer ? Wr1 : Wr0) + (size_t)r * 262144u
                      : (layer ? Wl1 : Wl0);
        dst = WT + (size_t)m * 262144u;
        R = 512; C = 512;
        tx = tile & 15; ty = tile >> 4;
    }
    int bx = tx * 32, by = ty * 32;
    int x = threadIdx.x, y = threadIdx.y;
#pragma unroll
    for (int j = 0; j < 32; j += 8)
        t[y + j][x] = src[(size_t)(by + y + j) * C + bx + x];
    __syncthreads();
#pragma unroll
    for (int j = 0; j < 32; j += 8)
        dst[(size_t)(bx + y + j) * R + by + x] = __float2half_rn(t[x][y + j]);
}

// ---------------------------------------------------------------------------

extern "C" void kernel_launch(void* const* d_in, const int* in_sizes, int n_in,
                              void* d_out, int out_size) {
    const float* attn = (const float*)d_in[0];
    const float* E    = (const float*)d_in[1];
    const float* Wemb = (const float*)d_in[2];
    const float* bemb = (const float*)d_in[3];
    const float* Wr0  = (const float*)d_in[4];
    const float* Wl0  = (const float*)d_in[5];
    const float* b0   = (const float*)d_in[6];
    const float* Wr1  = (const float*)d_in[7];
    const float* Wl1  = (const float*)d_in[8];
    const float* b1   = (const float*)d_in[9];
    float* out = (float*)d_out;

    __half *attnH, *EH, *WembT, *WT, *X0, *X1, *Z;
    cudaGetSymbolAddress((void**)&attnH, g_attnH);
    cudaGetSymbolAddress((void**)&EH, g_EH);
    cudaGetSymbolAddress((void**)&WembT, g_WembT);
    cudaGetSymbolAddress((void**)&WT, g_WT);
    cudaGetSymbolAddress((void**)&X0, g_X0);
    cudaGetSymbolAddress((void**)&X1, g_X1);
    cudaGetSymbolAddress((void**)&Z, g_Z);
    __half* WT0 = WT;
    __half* WT1 = WT + 7u * 262144u;

    cudaFuncSetAttribute(k_embed, cudaFuncAttributeMaxDynamicSharedMemorySize, SMEM_BYTES);
    cudaFuncSetAttribute(k_expand, cudaFuncAttributeMaxDynamicSharedMemorySize, SMEM_BYTES);
    cudaFuncSetAttribute(k_agg<true>, cudaFuncAttributeMaxDynamicSharedMemorySize, SMEM_BYTES);
    cudaFuncSetAttribute(k_agg<false>, cudaFuncAttributeMaxDynamicSharedMemorySize, SMEM_BYTES);

    k_tcvt_all<<<1024 + 14 * 256, dim3(32, 8)>>>(Wemb, Wr0, Wl0, Wr1, Wl1,
                                                 WembT, WT);
    k_cvt8<<<32768, 256>>>(attn, attnH, 32768 * 2048 / 8);
    k_cvtE<<<128u * 6u * 256u * 256u / 4u / 256u, 256>>>(E, EH);

    k_embed<<<dim3(4, 256), 256, SMEM_BYTES>>>(attnH, WembT, bemb, X0);

    k_expand<<<dim3(28, 256), 256, SMEM_BYTES>>>(X0, WT0, Z);
    k_agg<true><<<dim3(4, 2, 128), 256, SMEM_BYTES>>>(EH, Z, b0, X1);

    k_expand<<<dim3(28, 256), 256, SMEM_BYTES>>>(X1, WT1, Z);
    k_agg<false><<<dim3(4, 2, 128), 256, SMEM_BYTES>>>(EH, Z, b1, out);
}

// round 14
// speedup vs baseline: 1.1521x; 1.0152x over previous
#include <cuda_runtime.h>
#include <cuda_fp16.h>
#include <cstdint>

// ---------------------------------------------------------------------------
// RGCNEncoder via mma.sync fp16 tensor cores (m16n8k16, fp32 accumulate),
// ldmatrix fragment loads, BK=64 K-chunks, 3-stage cp.async pipeline,
// single __syncthreads per chunk. CTA tile 128x128, 8 warps x (64x32),
// __launch_bounds__(256,2) -> 2 CTAs/SM -> 4 warps/SMSP.
// B=128, R=6, N=256, D_IN=2048, D_H=512
//
//   x0 = relu(attn @ W_embed + b_embed)
//   layer l: Z[b,r] = x[b] @ W_rel_l[r] (r<6), Z6[b] = x[b] @ W_loop_l
//            out[b] = relu(sum_{r<6} E[b,r] @ Z[b,r] + Z6[b] + bias)
//
// Heterogeneous-block fusion: the E fp32->fp16 conversion rides inside the
// embed kernel (extra blocks), using idle DRAM bandwidth + the embed tail.
// ---------------------------------------------------------------------------

static __device__ __half g_attnH[32768u * 2048u];
static __device__ __half g_EH[128u * 6u * 256u * 256u];
static __device__ __half g_WembT[512u * 2048u];           // [h][din]
static __device__ __half g_WT[2][7u * 512u * 512u];       // [r][dout][din]
static __device__ __half g_X0[32768u * 512u];
static __device__ __half g_X1[32768u * 512u];
static __device__ __half g_Z[128u * 7u * 512u * 256u];    // slot6 = [n][d]

#define BK 64
#define RSTR 72   // BK + 8 pad (halves): 144B row stride, conflict-free ldmatrix

static constexpr uint32_t AS_BYTES = 128u * RSTR * 2;      // 18432 per operand
static constexpr uint32_t STAGE_BYTES = 2 * AS_BYTES;      // 36864
static constexpr int SMEM_BYTES = 3 * STAGE_BYTES;         // 110592 (x2 CTA = 221K)

// cvtE sizing: 128*6*256*256 floats = 12,582,912 float4s
//            = CVTE_BLOCKS(2048) * 256 threads * CVTE_ITERS(24)
static constexpr int CVTE_BLOCKS = 2048;
static constexpr int CVTE_ITERS = 24;
static_assert((size_t)CVTE_BLOCKS * 256 * CVTE_ITERS ==
              128u * 6u * 256u * 256u / 4u, "cvtE must cover all of E");

// ---- low-level helpers -----------------------------------------------------

__device__ __forceinline__ uint32_t smem_u32(const void* p) {
    uint32_t a;
    asm("{ .reg .u64 t; cvta.to.shared.u64 t, %1; cvt.u32.u64 %0, t; }"
        : "=r"(a) : "l"(p));
    return a;
}
__device__ __forceinline__ void cp_async16(uint32_t dst, const void* src) {
    asm volatile("cp.async.cg.shared.global [%0], [%1], 16;" ::"r"(dst), "l"(src));
}
__device__ __forceinline__ void cp_commit() {
    asm volatile("cp.async.commit_group;" ::: "memory");
}
template <int N>
__device__ __forceinline__ void cp_wait() {
    asm volatile("cp.async.wait_group %0;" ::"n"(N) : "memory");
}
__device__ __forceinline__ uint32_t h2u(__half2 h) {
    return *reinterpret_cast<uint32_t*>(&h);
}
__device__ __forceinline__ void ldm_x4(uint32_t& r0, uint32_t& r1, uint32_t& r2,
                                       uint32_t& r3, uint32_t addr) {
    asm volatile("ldmatrix.sync.aligned.m8n8.x4.shared.b16 {%0,%1,%2,%3}, [%4];"
                 : "=r"(r0), "=r"(r1), "=r"(r2), "=r"(r3) : "r"(addr));
}
__device__ __forceinline__ void mma16(float* c, const uint32_t* a, const uint32_t* b) {
    asm volatile(
        "mma.sync.aligned.m16n8k16.row.col.f32.f16.f16.f32 "
        "{%0,%1,%2,%3}, {%4,%5,%6,%7}, {%8,%9}, {%0,%1,%2,%3};"
        : "+f"(c[0]), "+f"(c[1]), "+f"(c[2]), "+f"(c[3])
        : "r"(a[0]), "r"(a[1]), "r"(a[2]), "r"(a[3]), "r"(b[0]), "r"(b[1]));
}

// 128 rows x 64 halves (128B/row) tile -> padded smem, 256 threads
__device__ __forceinline__ void ld_tile(uint32_t dst, const __half* __restrict__ src,
                                        int ldk, int tid) {
#pragma unroll
    for (int i = 0; i < 4; i++) {
        int idx = tid + i * 256;
        int row = idx >> 3, seg = idx & 7;
        cp_async16(dst + (uint32_t)(row * (RSTR * 2) + seg * 16),
                   src + (size_t)row * ldk + seg * 8);
    }
}

// ---- shared mainloop -------------------------------------------------------
// 8 warps, each a 64x32 warp tile (wm=(wid>>2)*64, wn=(wid&3)*32).
// Per k16 step: 4 A-ldmatrix.x4 + 2 B-ldmatrix.x4 feed 16 MMAs.
// 3-stage ring, single barrier per chunk.

template <class F>
__device__ __forceinline__ void gemm_main(const F& f, int nc, char* smraw,
                                          float acc[4][4][4]) {
    const int tid = threadIdx.x;
    const uint32_t sbase = smem_u32(smraw);
    const int lane = tid & 31, wid = tid >> 5;
    const int wm = (wid >> 2) * 64, wn = (wid & 3) * 32;

    const int l7 = lane & 7, lb3 = (lane >> 3) & 1, lb4 = lane >> 4;
    const uint32_t aOff = (uint32_t)((wm + l7 + lb3 * 8) * RSTR + lb4 * 8) * 2;
    const uint32_t bOff = AS_BYTES +
        (uint32_t)((wn + l7 + lb4 * 8) * RSTR + lb3 * 8) * 2;

    // prologue: stages 0, 1
#pragma unroll
    for (int p = 0; p < 2; p++) {
        if (p < nc) {
            ld_tile(sbase + p * STAGE_BYTES, f.a(p), f.lda, tid);
            ld_tile(sbase + p * STAGE_BYTES + AS_BYTES, f.b(p), f.ldb, tid);
        }
        cp_commit();
    }

    int stage = 0, nxt = 2;
    for (int c = 0; c < nc; c++) {
        if (c + 1 < nc) cp_wait<1>(); else cp_wait<0>();
        __syncthreads();
        if (c + 2 < nc) {
            ld_tile(sbase + nxt * STAGE_BYTES, f.a(c + 2), f.lda, tid);
            ld_tile(sbase + nxt * STAGE_BYTES + AS_BYTES, f.b(c + 2), f.ldb, tid);
            cp_commit();
        }
        const uint32_t abase = sbase + stage * STAGE_BYTES + aOff;
        const uint32_t bbase = sbase + stage * STAGE_BYTES + bOff;
#pragma unroll
        for (int kk = 0; kk < BK; kk += 16) {
            uint32_t a[4][4], b[4][2];
#pragma unroll
            for (int mt = 0; mt < 4; mt++)
                ldm_x4(a[mt][0], a[mt][1], a[mt][2], a[mt][3],
                       abase + (uint32_t)(mt * 16 * RSTR + kk) * 2);
#pragma unroll
            for (int p = 0; p < 2; p++)
                ldm_x4(b[2 * p][0], b[2 * p][1], b[2 * p + 1][0], b[2 * p + 1][1],
                       bbase + (uint32_t)(p * 16 * RSTR + kk) * 2);
#pragma unroll
            for (int mt = 0; mt < 4; mt++)
#pragma unroll
                for (int nt = 0; nt < 4; nt++) mma16(acc[mt][nt], a[mt], b[nt]);
        }
        stage = (stage == 2) ? 0 : stage + 1;
        nxt = (nxt == 2) ? 0 : nxt + 1;
    }
}

__device__ __forceinline__ void zero_acc(float acc[4][4][4]) {
#pragma unroll
    for (int i = 0; i < 4; i++)
#pragma unroll
        for (int j = 0; j < 4; j++)
#pragma unroll
            for (int k = 0; k < 4; k++) acc[i][j][k] = 0.f;
}

// ---- address functors ------------------------------------------------------

struct LinAddr {
    const __half *A, *B;
    int lda, ldb;
    __device__ const __half* a(int c) const { return A + c * BK; }
    __device__ const __half* b(int c) const { return B + c * BK; }
};
struct AggAddr {
    const __half *Eb, *Zb;
    int lda, ldb;
    __device__ const __half* a(int c) const {
        return Eb + (size_t)(c >> 2) * 65536u + (c & 3) * BK;
    }
    __device__ const __half* b(int c) const {
        return Zb + (size_t)(c >> 2) * 131072u + (c & 3) * BK;
    }
};

// ---- kernels ---------------------------------------------------------------

// Fused embed + E-conversion. grid (1024 + CVTE_BLOCKS).
// blocks [0,1024): X0[node][h] = relu(attnH @ WembT^T + bias), fp16 out
// blocks [1024,...): EH = fp16(E), 24 float4s/thread
__global__ void __launch_bounds__(256, 2) k_embed_cvtE(
    const __half* __restrict__ attn, const __half* __restrict__ WT,
    const float* __restrict__ bias, __half* __restrict__ out,
    const float* __restrict__ E, __half* __restrict__ EH) {
    extern __shared__ char smraw[];
    const int tid = threadIdx.x;

    if (blockIdx.x >= 1024) {
        // ---- cvtE path ----
        const int cb = blockIdx.x - 1024;
        const float4* s4 = (const float4*)E;
        uint2* d2 = (uint2*)EH;
#pragma unroll
        for (int k = 0; k < CVTE_ITERS; k++) {
            size_t i = (size_t)cb * 256 + tid + (size_t)k * CVTE_BLOCKS * 256;
            float4 v = s4[i];
            uint2 o;
            o.x = h2u(__floats2half2_rn(v.x, v.y));
            o.y = h2u(__floats2half2_rn(v.z, v.w));
            d2[i] = o;
        }
        return;
    }

    // ---- embed path ----
    const int bx = blockIdx.x & 3, by = blockIdx.x >> 2;
    float acc[4][4][4];
    zero_acc(acc);

    LinAddr f{attn + (size_t)by * 128 * 2048, WT + (size_t)bx * 128 * 2048,
              2048, 2048};
    gemm_main(f, 32, smraw, acc);

    const int lane = tid & 31, wid = tid >> 5;
    const int gid = lane >> 2, tig = lane & 3;
    const int wm = (wid >> 2) * 64, wn = (wid & 3) * 32;
#pragma unroll
    for (int mt = 0; mt < 4; mt++) {
        int row = by * 128 + wm + mt * 16 + gid;
#pragma unroll
        for (int nt = 0; nt < 4; nt++) {
            int col = bx * 128 + wn + nt * 8 + 2 * tig;
            float b0 = bias[col], b1 = bias[col + 1];
            __half2 h0 = __floats2half2_rn(fmaxf(acc[mt][nt][0] + b0, 0.f),
                                           fmaxf(acc[mt][nt][1] + b1, 0.f));
            __half2 h1 = __floats2half2_rn(fmaxf(acc[mt][nt][2] + b0, 0.f),
                                           fmaxf(acc[mt][nt][3] + b1, 0.f));
            *(uint32_t*)&out[(size_t)row * 512 + col] = h2u(h0);
            *(uint32_t*)&out[(size_t)(row + 8) * 512 + col] = h2u(h1);
        }
    }
}

// expand: grid (28, 256). r = bx>>2, d0 = (bx&3)*128.
//   r<6 : Z[b][r][d][j] = (WT[r] @ X^T)[d][node]   (transposed GEMM)
//   r==6: Z6[b][n][d]   = (X @ WT6^T)[node][d]     (natural GEMM, coalesced)
__global__ void __launch_bounds__(256, 2) k_expand(const __half* __restrict__ X,
                                                   const __half* __restrict__ WT,
                                                   __half* __restrict__ Z) {
    extern __shared__ char smraw[];
    const int bx = blockIdx.x, by = blockIdx.y;
    const int r = bx >> 2, d0 = (bx & 3) * 128;
    float acc[4][4][4];
    zero_acc(acc);

    const __half* Xp = X + (size_t)by * 128 * 512;
    const __half* Wp = WT + (size_t)r * 262144u + (size_t)d0 * 512;
    const bool loop_rel = (r == 6);
    LinAddr f = loop_rel ? LinAddr{Xp, Wp, 512, 512} : LinAddr{Wp, Xp, 512, 512};
    gemm_main(f, 8, smraw, acc);

    const int tid = threadIdx.x, lane = tid & 31, wid = tid >> 5;
    const int gid = lane >> 2, tig = lane & 3;
    const int wm = (wid >> 2) * 64, wn = (wid & 3) * 32;
    if (!loop_rel) {
#pragma unroll
        for (int mt = 0; mt < 4; mt++) {
            int d = d0 + wm + mt * 16 + gid;
#pragma unroll
            for (int nt = 0; nt < 4; nt++) {
                int m = by * 128 + wn + nt * 8 + 2 * tig;   // global node
                int b = m >> 8, j = m & 255;
                size_t zb = ((size_t)b * 7 + r) * 512u;
                __half2 h0 = __floats2half2_rn(acc[mt][nt][0], acc[mt][nt][1]);
                __half2 h1 = __floats2half2_rn(acc[mt][nt][2], acc[mt][nt][3]);
                *(uint32_t*)&Z[(zb + d) * 256u + j] = h2u(h0);
                *(uint32_t*)&Z[(zb + d + 8) * 256u + j] = h2u(h1);
            }
        }
    } else {
#pragma unroll
        for (int mt = 0; mt < 4; mt++) {
            int m = by * 128 + wm + mt * 16 + gid;          // global node
            int b = m >> 8, n = m & 255;
            size_t z6 = ((size_t)b * 7 + 6) * 131072u;
#pragma unroll
            for (int nt = 0; nt < 4; nt++) {
                int d = d0 + wn + nt * 8 + 2 * tig;
                __half2 h0 = __floats2half2_rn(acc[mt][nt][0], acc[mt][nt][1]);
                __half2 h1 = __floats2half2_rn(acc[mt][nt][2], acc[mt][nt][3]);
                *(uint32_t*)&Z[z6 + (size_t)n * 512 + d] = h2u(h0);
                *(uint32_t*)&Z[z6 + (size_t)(n + 8) * 512 + d] = h2u(h1);
            }
        }
    }
}

// agg: grid (4, 2, 128).
// out[b,i,d] = relu(sum_{r<6,j} EH[b,r,i,j]*Z[b,r,d,j] + Z6[b,i,d] + bias[d])
template <bool HALF_OUT>
__global__ void __launch_bounds__(256, 2) k_agg(const __half* __restrict__ EH,
                                                const __half* __restrict__ Z,
                                                const float* __restrict__ bias,
                                                void* __restrict__ outv) {
    extern __shared__ char smraw[];
    const int bx = blockIdx.x, by = blockIdx.y, b = blockIdx.z;
    float acc[4][4][4];
    zero_acc(acc);

    AggAddr f{EH + (size_t)b * 393216u + (size_t)(by * 128) * 256u,
              Z + (size_t)b * 917504u + (size_t)(bx * 128) * 256u, 256, 256};
    gemm_main(f, 24, smraw, acc);

    const __half* Z6 = Z + (size_t)b * 917504u + 6u * 131072u;   // [n][d]
    const int tid = threadIdx.x, lane = tid & 31, wid = tid >> 5;
    const int gid = lane >> 2, tig = lane & 3;
    const int wm = (wid >> 2) * 64, wn = (wid & 3) * 32;
#pragma unroll
    for (int mt = 0; mt < 4; mt++) {
        int i = by * 128 + wm + mt * 16 + gid;
#pragma unroll
        for (int nt = 0; nt < 4; nt++) {
            int d = bx * 128 + wn + nt * 8 + 2 * tig;
            float b0 = bias[d], b1 = bias[d + 1];
            __half2 s0 = *(const __half2*)&Z6[(size_t)i * 512 + d];
            __half2 s1 = *(const __half2*)&Z6[(size_t)(i + 8) * 512 + d];
            float2 f0 = __half22float2(s0), f1 = __half22float2(s1);
            float r0 = fmaxf(acc[mt][nt][0] + f0.x + b0, 0.f);
            float r1 = fmaxf(acc[mt][nt][1] + f0.y + b1, 0.f);
            float r2 = fmaxf(acc[mt][nt][2] + f1.x + b0, 0.f);
            float r3 = fmaxf(acc[mt][nt][3] + f1.y + b1, 0.f);
            size_t o0 = ((size_t)b * 256 + i) * 512 + d;
            size_t o1 = ((size_t)b * 256 + i + 8) * 512 + d;
            if (HALF_OUT) {
                __half* out = (__half*)outv;
                *(uint32_t*)&out[o0] = h2u(__floats2half2_rn(r0, r1));
                *(uint32_t*)&out[o1] = h2u(__floats2half2_rn(r2, r3));
            } else {
                float* out = (float*)outv;
                *(float2*)&out[o0] = make_float2(r0, r1);
                *(float2*)&out[o1] = make_float2(r2, r3);
            }
        }
    }
}

// ---- fused prep: weight transpose+convert AND attn convert, one launch -----
// blocks [0,1024)          : Wemb tiles (2048x512 -> WembT 512x2048)
// blocks [1024, 1024+3584) : 14 mats of 512x512 -> WT
// blocks [4608, 4608+32768): attn fp32 -> fp16 (uint4 of 8 halves / thread)
__global__ void k_prep(const float* __restrict__ Wemb,
                       const float* __restrict__ Wr0,
                       const float* __restrict__ Wl0,
                       const float* __restrict__ Wr1,
                       const float* __restrict__ Wl1,
                       __half* __restrict__ WembT,
                       __half* __restrict__ WT,
                       const float* __restrict__ attn,
                       __half* __restrict__ attnH) {
    int bid = blockIdx.x;
    int tid = threadIdx.x;
    if (bid >= 4608) {
        int i = (bid - 4608) * 256 + tid;   // < 8388608
        const float4* s4 = (const float4*)attn;
        float4 v0 = s4[2 * (size_t)i], v1 = s4[2 * (size_t)i + 1];
        uint4 o;
        o.x = h2u(__floats2half2_rn(v0.x, v0.y));
        o.y = h2u(__floats2half2_rn(v0.z, v0.w));
        o.z = h2u(__floats2half2_rn(v1.x, v1.y));
        o.w = h2u(__floats2half2_rn(v1.z, v1.w));
        ((uint4*)attnH)[i] = o;
        return;
    }
    __shared__ float t[32][33];
    const float* src;
    __half* dst;
    int R, C, tx, ty;
    if (bid < 1024) {
        src = Wemb; dst = WembT; R = 2048; C = 512;
        tx = bid & 15; ty = bid >> 4;
    } else {
        int idx = bid - 1024;
        int m = idx >> 8, tile = idx & 255;
        int layer = m / 7, r = m % 7;
        src = (r < 6) ? (layer ? Wr1 : Wr0) + (size_t)r * 262144u
                      : (layer ? Wl1 : Wl0);
        dst = WT + (size_t)m * 262144u;
        R = 512; C = 512;
        tx = tile & 15; ty = tile >> 4;
    }
    int bx = tx * 32, by = ty * 32;
    int x = tid & 31, y = tid >> 5;   // 32x8 logical
#pragma unroll
    for (int j = 0; j < 32; j += 8)
        t[y + j][x] = src[(size_t)(by + y + j) * C + bx + x];
    __syncthreads();
#pragma unroll
    for (int j = 0; j < 32; j += 8)
        dst[(size_t)(bx + y + j) * R + by + x] = __float2half_rn(t[x][y + j]);
}

// ---------------------------------------------------------------------------

extern "C" void kernel_launch(void* const* d_in, const int* in_sizes, int n_in,
                              void* d_out, int out_size) {
    const float* attn = (const float*)d_in[0];
    const float* E    = (const float*)d_in[1];
    const float* Wemb = (const float*)d_in[2];
    const float* bemb = (const float*)d_in[3];
    const float* Wr0  = (const float*)d_in[4];
    const float* Wl0  = (const float*)d_in[5];
    const float* b0   = (const float*)d_in[6];
    const float* Wr1  = (const float*)d_in[7];
    const float* Wl1  = (const float*)d_in[8];
    const float* b1   = (const float*)d_in[9];
    float* out = (float*)d_out;

    __half *attnH, *EH, *WembT, *WT, *X0, *X1, *Z;
    cudaGetSymbolAddress((void**)&attnH, g_attnH);
    cudaGetSymbolAddress((void**)&EH, g_EH);
    cudaGetSymbolAddress((void**)&WembT, g_WembT);
    cudaGetSymbolAddress((void**)&WT, g_WT);
    cudaGetSymbolAddress((void**)&X0, g_X0);
    cudaGetSymbolAddress((void**)&X1, g_X1);
    cudaGetSymbolAddress((void**)&Z, g_Z);
    __half* WT0 = WT;
    __half* WT1 = WT + 7u * 262144u;

    cudaFuncSetAttribute(k_embed_cvtE, cudaFuncAttributeMaxDynamicSharedMemorySize, SMEM_BYTES);
    cudaFuncSetAttribute(k_expand, cudaFuncAttributeMaxDynamicSharedMemorySize, SMEM_BYTES);
    cudaFuncSetAttribute(k_agg<true>, cudaFuncAttributeMaxDynamicSharedMemorySize, SMEM_BYTES);
    cudaFuncSetAttribute(k_agg<false>, cudaFuncAttributeMaxDynamicSharedMemorySize, SMEM_BYTES);

    k_prep<<<4608 + 32768, 256>>>(Wemb, Wr0, Wl0, Wr1, Wl1, WembT, WT,
                                  attn, attnH);

    k_embed_cvtE<<<1024 + CVTE_BLOCKS, 256, SMEM_BYTES>>>(attnH, WembT, bemb,
                                                          X0, E, EH);

    k_expand<<<dim3(28, 256), 256, SMEM_BYTES>>>(X0, WT0, Z);
    k_agg<true><<<dim3(4, 2, 128), 256, SMEM_BYTES>>>(EH, Z, b0, X1);

    k_expand<<<dim3(28, 256), 256, SMEM_BYTES>>>(X1, WT1, Z);
    k_agg<false><<<dim3(4, 2, 128), 256, SMEM_BYTES>>>(EH, Z, b1, out);
}

// round 15
// speedup vs baseline: 1.2277x; 1.0656x over previous
#include <cuda_runtime.h>
#include <cuda_fp16.h>
#include <cstdint>

// ---------------------------------------------------------------------------
// RGCNEncoder via mma.sync fp16 tensor cores (m16n8k16, fp32 accumulate),
// ldmatrix fragment loads, BK=64 K-chunks, 3-stage cp.async pipeline,
// single __syncthreads per chunk. CTA tile 128x128, 8 warps x (64x32),
// __launch_bounds__(256,2) -> 2 CTAs/SM -> 4 warps/SMSP.
// All epilogues are smem-staged for fully-coalesced 16B global stores;
// agg's Z6 operand is cp.async-staged through smem likewise.
// B=128, R=6, N=256, D_IN=2048, D_H=512
// ---------------------------------------------------------------------------

static __device__ __half g_attnH[32768u * 2048u];
static __device__ __half g_EH[128u * 6u * 256u * 256u];
static __device__ __half g_WembT[512u * 2048u];           // [h][din]
static __device__ __half g_WT[2][7u * 512u * 512u];       // [r][dout][din]
static __device__ __half g_X0[32768u * 512u];
static __device__ __half g_X1[32768u * 512u];
static __device__ __half g_Z[128u * 7u * 512u * 256u];    // slot6 = [n][d]

#define BK 64
#define RSTR 72   // BK + 8 pad (halves): 144B row stride, conflict-free ldmatrix

static constexpr uint32_t AS_BYTES = 128u * RSTR * 2;      // 18432 per operand
static constexpr uint32_t STAGE_BYTES = 2 * AS_BYTES;      // 36864
static constexpr int SMEM_BYTES = 3 * STAGE_BYTES;         // 110592 (x2 CTA = 221K)

// epilogue staging: 128 x 136 (PAD) tiles; conflict-free frag writes
#define EPAD 136
static constexpr uint32_t SZ6_BYTES = 128u * EPAD * 2;     // 34816 (agg Z6 stage)
// half sT: 34816 bytes; float sT: 69632 bytes. agg worst: 34816+69632=104448 OK

// cvtE sizing: 128*6*256*256 floats = 12,582,912 float4s
static constexpr int CVTE_BLOCKS = 2048;
static constexpr int CVTE_ITERS = 24;
static_assert((size_t)CVTE_BLOCKS * 256 * CVTE_ITERS ==
              128u * 6u * 256u * 256u / 4u, "cvtE must cover all of E");

// ---- low-level helpers -----------------------------------------------------

__device__ __forceinline__ uint32_t smem_u32(const void* p) {
    uint32_t a;
    asm("{ .reg .u64 t; cvta.to.shared.u64 t, %1; cvt.u32.u64 %0, t; }"
        : "=r"(a) : "l"(p));
    return a;
}
__device__ __forceinline__ void cp_async16(uint32_t dst, const void* src) {
    asm volatile("cp.async.cg.shared.global [%0], [%1], 16;" ::"r"(dst), "l"(src));
}
__device__ __forceinline__ void cp_commit() {
    asm volatile("cp.async.commit_group;" ::: "memory");
}
template <int N>
__device__ __forceinline__ void cp_wait() {
    asm volatile("cp.async.wait_group %0;" ::"n"(N) : "memory");
}
__device__ __forceinline__ uint32_t h2u(__half2 h) {
    return *reinterpret_cast<uint32_t*>(&h);
}
__device__ __forceinline__ void ldm_x4(uint32_t& r0, uint32_t& r1, uint32_t& r2,
                                       uint32_t& r3, uint32_t addr) {
    asm volatile("ldmatrix.sync.aligned.m8n8.x4.shared.b16 {%0,%1,%2,%3}, [%4];"
                 : "=r"(r0), "=r"(r1), "=r"(r2), "=r"(r3) : "r"(addr));
}
__device__ __forceinline__ void mma16(float* c, const uint32_t* a, const uint32_t* b) {
    asm volatile(
        "mma.sync.aligned.m16n8k16.row.col.f32.f16.f16.f32 "
        "{%0,%1,%2,%3}, {%4,%5,%6,%7}, {%8,%9}, {%0,%1,%2,%3};"
        : "+f"(c[0]), "+f"(c[1]), "+f"(c[2]), "+f"(c[3])
        : "r"(a[0]), "r"(a[1]), "r"(a[2]), "r"(a[3]), "r"(b[0]), "r"(b[1]));
}

// 128 rows x 64 halves (128B/row) tile -> padded smem, 256 threads
__device__ __forceinline__ void ld_tile(uint32_t dst, const __half* __restrict__ src,
                                        int ldk, int tid) {
#pragma unroll
    for (int i = 0; i < 4; i++) {
        int idx = tid + i * 256;
        int row = idx >> 3, seg = idx & 7;
        cp_async16(dst + (uint32_t)(row * (RSTR * 2) + seg * 16),
                   src + (size_t)row * ldk + seg * 8);
    }
}

// coalesced copy-out: 128x128 half tile (PAD=136) -> gmem rows (stride halves)
__device__ __forceinline__ void copy_out_h(const __half* sT, __half* g,
                                           int gstride, int tid) {
#pragma unroll
    for (int i = 0; i < 8; i++) {
        int idx = tid + i * 256;
        int row = idx >> 4, seg = idx & 15;
        uint4 v = *(const uint4*)(sT + row * EPAD + seg * 8);
        *(uint4*)(g + (size_t)row * gstride + seg * 8) = v;
    }
}
// coalesced copy-out: 128x128 float tile (PAD=136 floats) -> gmem
__device__ __forceinline__ void copy_out_f(const float* sT, float* g,
                                           int gstride, int tid) {
#pragma unroll
    for (int i = 0; i < 16; i++) {
        int idx = tid + i * 256;
        int row = idx >> 5, seg = idx & 31;
        uint4 v = *(const uint4*)(sT + row * EPAD + seg * 4);
        *(uint4*)(g + (size_t)row * gstride + seg * 4) = v;
    }
}

// ---- shared mainloop -------------------------------------------------------

template <class F>
__device__ __forceinline__ void gemm_main(const F& f, int nc, char* smraw,
                                          float acc[4][4][4]) {
    const int tid = threadIdx.x;
    const uint32_t sbase = smem_u32(smraw);
    const int lane = tid & 31, wid = tid >> 5;
    const int wm = (wid >> 2) * 64, wn = (wid & 3) * 32;

    const int l7 = lane & 7, lb3 = (lane >> 3) & 1, lb4 = lane >> 4;
    const uint32_t aOff = (uint32_t)((wm + l7 + lb3 * 8) * RSTR + lb4 * 8) * 2;
    const uint32_t bOff = AS_BYTES +
        (uint32_t)((wn + l7 + lb4 * 8) * RSTR + lb3 * 8) * 2;

#pragma unroll
    for (int p = 0; p < 2; p++) {
        if (p < nc) {
            ld_tile(sbase + p * STAGE_BYTES, f.a(p), f.lda, tid);
            ld_tile(sbase + p * STAGE_BYTES + AS_BYTES, f.b(p), f.ldb, tid);
        }
        cp_commit();
    }

    int stage = 0, nxt = 2;
    for (int c = 0; c < nc; c++) {
        if (c + 1 < nc) cp_wait<1>(); else cp_wait<0>();
        __syncthreads();
        if (c + 2 < nc) {
            ld_tile(sbase + nxt * STAGE_BYTES, f.a(c + 2), f.lda, tid);
            ld_tile(sbase + nxt * STAGE_BYTES + AS_BYTES, f.b(c + 2), f.ldb, tid);
            cp_commit();
        }
        const uint32_t abase = sbase + stage * STAGE_BYTES + aOff;
        const uint32_t bbase = sbase + stage * STAGE_BYTES + bOff;
#pragma unroll
        for (int kk = 0; kk < BK; kk += 16) {
            uint32_t a[4][4], b[4][2];
#pragma unroll
            for (int mt = 0; mt < 4; mt++)
                ldm_x4(a[mt][0], a[mt][1], a[mt][2], a[mt][3],
                       abase + (uint32_t)(mt * 16 * RSTR + kk) * 2);
#pragma unroll
            for (int p = 0; p < 2; p++)
                ldm_x4(b[2 * p][0], b[2 * p][1], b[2 * p + 1][0], b[2 * p + 1][1],
                       bbase + (uint32_t)(p * 16 * RSTR + kk) * 2);
#pragma unroll
            for (int mt = 0; mt < 4; mt++)
#pragma unroll
                for (int nt = 0; nt < 4; nt++) mma16(acc[mt][nt], a[mt], b[nt]);
        }
        stage = (stage == 2) ? 0 : stage + 1;
        nxt = (nxt == 2) ? 0 : nxt + 1;
    }
}

__device__ __forceinline__ void zero_acc(float acc[4][4][4]) {
#pragma unroll
    for (int i = 0; i < 4; i++)
#pragma unroll
        for (int j = 0; j < 4; j++)
#pragma unroll
            for (int k = 0; k < 4; k++) acc[i][j][k] = 0.f;
}

// ---- address functors ------------------------------------------------------

struct LinAddr {
    const __half *A, *B;
    int lda, ldb;
    __device__ const __half* a(int c) const { return A + c * BK; }
    __device__ const __half* b(int c) const { return B + c * BK; }
};
struct AggAddr {
    const __half *Eb, *Zb;
    int lda, ldb;
    __device__ const __half* a(int c) const {
        return Eb + (size_t)(c >> 2) * 65536u + (c & 3) * BK;
    }
    __device__ const __half* b(int c) const {
        return Zb + (size_t)(c >> 2) * 131072u + (c & 3) * BK;
    }
};

// ---- kernels ---------------------------------------------------------------

// Fused embed + E-conversion. grid (1024 + CVTE_BLOCKS).
__global__ void __launch_bounds__(256, 2) k_embed_cvtE(
    const __half* __restrict__ attn, const __half* __restrict__ WT,
    const float* __restrict__ bias, __half* __restrict__ out,
    const float* __restrict__ E, __half* __restrict__ EH) {
    extern __shared__ char smraw[];
    const int tid = threadIdx.x;

    if (blockIdx.x >= 1024) {
        const int cb = blockIdx.x - 1024;
        const float4* s4 = (const float4*)E;
        uint2* d2 = (uint2*)EH;
#pragma unroll
        for (int k = 0; k < CVTE_ITERS; k++) {
            size_t i = (size_t)cb * 256 + tid + (size_t)k * CVTE_BLOCKS * 256;
            float4 v = s4[i];
            uint2 o;
            o.x = h2u(__floats2half2_rn(v.x, v.y));
            o.y = h2u(__floats2half2_rn(v.z, v.w));
            d2[i] = o;
        }
        return;
    }

    const int bx = blockIdx.x & 3, by = blockIdx.x >> 2;
    float acc[4][4][4];
    zero_acc(acc);

    LinAddr f{attn + (size_t)by * 128 * 2048, WT + (size_t)bx * 128 * 2048,
              2048, 2048};
    gemm_main(f, 32, smraw, acc);

    const int lane = tid & 31, wid = tid >> 5;
    const int gid = lane >> 2, tig = lane & 3;
    const int wm = (wid >> 2) * 64, wn = (wid & 3) * 32;
    __half* sT = (__half*)smraw;
    __syncthreads();
#pragma unroll
    for (int mt = 0; mt < 4; mt++) {
        int row = wm + mt * 16 + gid;
#pragma unroll
        for (int nt = 0; nt < 4; nt++) {
            int col = wn + nt * 8 + 2 * tig;
            float b0 = bias[bx * 128 + col], b1 = bias[bx * 128 + col + 1];
            __half2 h0 = __floats2half2_rn(fmaxf(acc[mt][nt][0] + b0, 0.f),
                                           fmaxf(acc[mt][nt][1] + b1, 0.f));
            __half2 h1 = __floats2half2_rn(fmaxf(acc[mt][nt][2] + b0, 0.f),
                                           fmaxf(acc[mt][nt][3] + b1, 0.f));
            *(uint32_t*)&sT[row * EPAD + col] = h2u(h0);
            *(uint32_t*)&sT[(row + 8) * EPAD + col] = h2u(h1);
        }
    }
    __syncthreads();
    copy_out_h(sT, out + (size_t)(by * 128) * 512 + bx * 128, 512, tid);
}

// expand: grid (28, 256). r = bx>>2, d0 = (bx&3)*128.
__global__ void __launch_bounds__(256, 2) k_expand(const __half* __restrict__ X,
                                                   const __half* __restrict__ WT,
                                                   __half* __restrict__ Z) {
    extern __shared__ char smraw[];
    const int bx = blockIdx.x, by = blockIdx.y;
    const int r = bx >> 2, d0 = (bx & 3) * 128;
    float acc[4][4][4];
    zero_acc(acc);

    const __half* Xp = X + (size_t)by * 128 * 512;
    const __half* Wp = WT + (size_t)r * 262144u + (size_t)d0 * 512;
    const bool loop_rel = (r == 6);
    LinAddr f = loop_rel ? LinAddr{Xp, Wp, 512, 512} : LinAddr{Wp, Xp, 512, 512};
    gemm_main(f, 8, smraw, acc);

    const int tid = threadIdx.x, lane = tid & 31, wid = tid >> 5;
    const int gid = lane >> 2, tig = lane & 3;
    const int wm = (wid >> 2) * 64, wn = (wid & 3) * 32;
    const int b = (by * 128) >> 8;
    const int off = (by * 128) & 255;   // j0 (r<6) or n0 (r==6)
    __half* sT = (__half*)smraw;
    __syncthreads();
#pragma unroll
    for (int mt = 0; mt < 4; mt++) {
        int row = wm + mt * 16 + gid;
#pragma unroll
        for (int nt = 0; nt < 4; nt++) {
            int col = wn + nt * 8 + 2 * tig;
            __half2 h0 = __floats2half2_rn(acc[mt][nt][0], acc[mt][nt][1]);
            __half2 h1 = __floats2half2_rn(acc[mt][nt][2], acc[mt][nt][3]);
            *(uint32_t*)&sT[row * EPAD + col] = h2u(h0);
            *(uint32_t*)&sT[(row + 8) * EPAD + col] = h2u(h1);
        }
    }
    __syncthreads();
    if (!loop_rel) {
        // rows = d (at d0), cols = j (at off); stride 256
        __half* g = Z + (((size_t)b * 7 + r) * 512 + d0) * 256u + off;
        copy_out_h(sT, g, 256, tid);
    } else {
        // rows = n (at off), cols = d (at d0); stride 512
        __half* g = Z + ((size_t)b * 7 + 6) * 131072u + (size_t)off * 512 + d0;
        copy_out_h(sT, g, 512, tid);
    }
}

// agg: grid (4, 2, 128).
template <bool HALF_OUT>
__global__ void __launch_bounds__(256, 2) k_agg(const __half* __restrict__ EH,
                                                const __half* __restrict__ Z,
                                                const float* __restrict__ bias,
                                                void* __restrict__ outv) {
    extern __shared__ char smraw[];
    const int bx = blockIdx.x, by = blockIdx.y, b = blockIdx.z;
    float acc[4][4][4];
    zero_acc(acc);

    AggAddr f{EH + (size_t)b * 393216u + (size_t)(by * 128) * 256u,
              Z + (size_t)b * 917504u + (size_t)(bx * 128) * 256u, 256, 256};
    gemm_main(f, 24, smraw, acc);

    const int tid = threadIdx.x, lane = tid & 31, wid = tid >> 5;
    const int gid = lane >> 2, tig = lane & 3;
    const int wm = (wid >> 2) * 64, wn = (wid & 3) * 32;
    const uint32_t sbase = smem_u32(smraw);

    // stage Z6 tile [i 128][d 128] coalesced into smem (overlaps stage 0 only,
    // which no warp touches during the final two chunks)
    const __half* Z6src = Z + (size_t)b * 917504u + 6u * 131072u +
                          (size_t)(by * 128) * 512 + bx * 128;
#pragma unroll
    for (int i2 = 0; i2 < 8; i2++) {
        int idx = tid + i2 * 256;
        int row = idx >> 4, seg = idx & 15;
        cp_async16(sbase + (uint32_t)(row * (EPAD * 2) + seg * 16),
                   Z6src + (size_t)row * 512 + seg * 8);
    }
    cp_commit();
    cp_wait<0>();
    __syncthreads();

    const __half* sZ6 = (const __half*)smraw;
    if (HALF_OUT) {
        __half* sT = (__half*)(smraw + SZ6_BYTES);
#pragma unroll
        for (int mt = 0; mt < 4; mt++) {
            int row = wm + mt * 16 + gid;
#pragma unroll
            for (int nt = 0; nt < 4; nt++) {
                int col = wn + nt * 8 + 2 * tig;
                float b0 = bias[bx * 128 + col], b1 = bias[bx * 128 + col + 1];
                float2 f0 = __half22float2(*(const __half2*)&sZ6[row * EPAD + col]);
                float2 f1 = __half22float2(*(const __half2*)&sZ6[(row + 8) * EPAD + col]);
                __half2 h0 = __floats2half2_rn(fmaxf(acc[mt][nt][0] + f0.x + b0, 0.f),
                                               fmaxf(acc[mt][nt][1] + f0.y + b1, 0.f));
                __half2 h1 = __floats2half2_rn(fmaxf(acc[mt][nt][2] + f1.x + b0, 0.f),
                                               fmaxf(acc[mt][nt][3] + f1.y + b1, 0.f));
                *(uint32_t*)&sT[row * EPAD + col] = h2u(h0);
                *(uint32_t*)&sT[(row + 8) * EPAD + col] = h2u(h1);
            }
        }
        __syncthreads();
        __half* g = (__half*)outv + ((size_t)b * 256 + by * 128) * 512 + bx * 128;
        copy_out_h(sT, g, 512, tid);
    } else {
        float* sT = (float*)(smraw + SZ6_BYTES);
#pragma unroll
        for (int mt = 0; mt < 4; mt++) {
            int row = wm + mt * 16 + gid;
#pragma unroll
            for (int nt = 0; nt < 4; nt++) {
                int col = wn + nt * 8 + 2 * tig;
                float b0 = bias[bx * 128 + col], b1 = bias[bx * 128 + col + 1];
                float2 f0 = __half22float2(*(const __half2*)&sZ6[row * EPAD + col]);
                float2 f1 = __half22float2(*(const __half2*)&sZ6[(row + 8) * EPAD + col]);
                *(float2*)&sT[row * EPAD + col] =
                    make_float2(fmaxf(acc[mt][nt][0] + f0.x + b0, 0.f),
                                fmaxf(acc[mt][nt][1] + f0.y + b1, 0.f));
                *(float2*)&sT[(row + 8) * EPAD + col] =
                    make_float2(fmaxf(acc[mt][nt][2] + f1.x + b0, 0.f),
                                fmaxf(acc[mt][nt][3] + f1.y + b1, 0.f));
            }
        }
        __syncthreads();
        float* g = (float*)outv + ((size_t)b * 256 + by * 128) * 512 + bx * 128;
        copy_out_f(sT, g, 512, tid);
    }
}

// ---- fused prep: weight transpose+convert AND attn convert, one launch -----
__global__ void k_prep(const float* __restrict__ Wemb,
                       const float* __restrict__ Wr0,
                       const float* __restrict__ Wl0,
                       const float* __restrict__ Wr1,
                       const float* __restrict__ Wl1,
                       __half* __restrict__ WembT,
                       __half* __restrict__ WT,
                       const float* __restrict__ attn,
                       __half* __restrict__ attnH) {
    int bid = blockIdx.x;
    int tid = threadIdx.x;
    if (bid >= 4608) {
        int i = (bid - 4608) * 256 + tid;
        const float4* s4 = (const float4*)attn;
        float4 v0 = s4[2 * (size_t)i], v1 = s4[2 * (size_t)i + 1];
        uint4 o;
        o.x = h2u(__floats2half2_rn(v0.x, v0.y));
        o.y = h2u(__floats2half2_rn(v0.z, v0.w));
        o.z = h2u(__floats2half2_rn(v1.x, v1.y));
        o.w = h2u(__floats2half2_rn(v1.z, v1.w));
        ((uint4*)attnH)[i] = o;
        return;
    }
    __shared__ float t[32][33];
    const float* src;
    __half* dst;
    int R, C, tx, ty;
    if (bid < 1024) {
        src = Wemb; dst = WembT; R = 2048; C = 512;
        tx = bid & 15; ty = bid >> 4;
    } else {
        int idx = bid - 1024;
        int m = idx >> 8, tile = idx & 255;
        int layer = m / 7, r = m % 7;
        src = (r < 6) ? (layer ? Wr1 : Wr0) + (size_t)r * 262144u
                      : (layer ? Wl1 : Wl0);
        dst = WT + (size_t)m * 262144u;
        R = 512; C = 512;
        tx = tile & 15; ty = tile >> 4;
    }
    int bx = tx * 32, by = ty * 32;
    int x = tid & 31, y = tid >> 5;
#pragma unroll
    for (int j = 0; j < 32; j += 8)
        t[y + j][x] = src[(size_t)(by + y + j) * C + bx + x];
    __syncthreads();
#pragma unroll
    for (int j = 0; j < 32; j += 8)
        dst[(size_t)(bx + y + j) * R + by + x] = __float2half_rn(t[x][y + j]);
}

// ---------------------------------------------------------------------------

extern "C" void kernel_launch(void* const* d_in, const int* in_sizes, int n_in,
                              void* d_out, int out_size) {
    const float* attn = (const float*)d_in[0];
    const float* E    = (const float*)d_in[1];
    const float* Wemb = (const float*)d_in[2];
    const float* bemb = (const float*)d_in[3];
    const float* Wr0  = (const float*)d_in[4];
    const float* Wl0  = (const float*)d_in[5];
    const float* b0   = (const float*)d_in[6];
    const float* Wr1  = (const float*)d_in[7];
    const float* Wl1  = (const float*)d_in[8];
    const float* b1   = (const float*)d_in[9];
    float* out = (float*)d_out;

    __half *attnH, *EH, *WembT, *WT, *X0, *X1, *Z;
    cudaGetSymbolAddress((void**)&attnH, g_attnH);
    cudaGetSymbolAddress((void**)&EH, g_EH);
    cudaGetSymbolAddress((void**)&WembT, g_WembT);
    cudaGetSymbolAddress((void**)&WT, g_WT);
    cudaGetSymbolAddress((void**)&X0, g_X0);
    cudaGetSymbolAddress((void**)&X1, g_X1);
    cudaGetSymbolAddress((void**)&Z, g_Z);
    __half* WT0 = WT;
    __half* WT1 = WT + 7u * 262144u;

    cudaFuncSetAttribute(k_embed_cvtE, cudaFuncAttributeMaxDynamicSharedMemorySize, SMEM_BYTES);
    cudaFuncSetAttribute(k_expand, cudaFuncAttributeMaxDynamicSharedMemorySize, SMEM_BYTES);
    cudaFuncSetAttribute(k_agg<true>, cudaFuncAttributeMaxDynamicSharedMemorySize, SMEM_BYTES);
    cudaFuncSetAttribute(k_agg<false>, cudaFuncAttributeMaxDynamicSharedMemorySize, SMEM_BYTES);

    k_prep<<<4608 + 32768, 256>>>(Wemb, Wr0, Wl0, Wr1, Wl1, WembT, WT,
                                  attn, attnH);

    k_embed_cvtE<<<1024 + CVTE_BLOCKS, 256, SMEM_BYTES>>>(attnH, WembT, bemb,
                                                          X0, E, EH);

    k_expand<<<dim3(28, 256), 256, SMEM_BYTES>>>(X0, WT0, Z);
    k_agg<true><<<dim3(4, 2, 128), 256, SMEM_BYTES>>>(EH, Z, b0, X1);

    k_expand<<<dim3(28, 256), 256, SMEM_BYTES>>>(X1, WT1, Z);
    k_agg<false><<<dim3(4, 2, 128), 256, SMEM_BYTES>>>(EH, Z, b1, out);
}